// round 16
// baseline (speedup 1.0000x reference)
#include <cuda_runtime.h>
#include <cuda_fp16.h>
#include <cstdint>

// Problem constants
#define BATCH 2
#define SEQ   2048
#define DMODEL 1024
#define NHEAD 16
#define HDIM  64
#define MROWS (BATCH*SEQ)          // 4096
#define NEG_INF_V (-1.0e9f)
#define QSCALE (0.125f * 1.4426950408889634f)   // 1/sqrt(64) * log2(e)

// ---------------- scratch (no allocation allowed) ----------------
__device__ __half g_A[3u*MROWS*DMODEL];        // fp16 q,k,v (natural)
__device__ __half g_W[4u*DMODEL*DMODEL];       // fp16 Wq,Wk,Wv,Wo (natural)
__device__ __half g_Q[BATCH*NHEAD*SEQ*HDIM];   // [B,H,L,Hd] scaled by QSCALE
__device__ __half g_K[BATCH*NHEAD*SEQ*HDIM];   // [B,H,L,Hd]
__device__ __half g_V[BATCH*NHEAD*SEQ*HDIM];   // [B,H,L,Hd]
__device__ __half g_O[BATCH*SEQ*DMODEL];       // [B,L,D]

// ---------------- helpers ----------------
__device__ __forceinline__ uint32_t pack2(float a, float b) {
    __half2 h = __floats2half2_rn(a, b);
    return *(uint32_t*)&h;
}
__device__ __forceinline__ float ex2f(float x) {
    float r;
    asm("ex2.approx.ftz.f32 %0, %1;" : "=f"(r) : "f"(x));
    return r;
}
__device__ __forceinline__ void mma_f16(float c[4], uint32_t a0, uint32_t a1,
                                        uint32_t a2, uint32_t a3,
                                        uint32_t b0, uint32_t b1) {
    asm volatile(
        "mma.sync.aligned.m16n8k16.row.col.f32.f16.f16.f32 "
        "{%0,%1,%2,%3},{%4,%5,%6,%7},{%8,%9},{%0,%1,%2,%3};"
        : "+f"(c[0]), "+f"(c[1]), "+f"(c[2]), "+f"(c[3])
        : "r"(a0), "r"(a1), "r"(a2), "r"(a3), "r"(b0), "r"(b1));
}
__device__ __forceinline__ void ldsm_x4(uint32_t& r0, uint32_t& r1,
                                        uint32_t& r2, uint32_t& r3, uint32_t addr) {
    asm volatile("ldmatrix.sync.aligned.m8n8.x4.shared.b16 {%0,%1,%2,%3}, [%4];"
                 : "=r"(r0), "=r"(r1), "=r"(r2), "=r"(r3) : "r"(addr));
}
__device__ __forceinline__ void ldsm_x4_t(uint32_t& r0, uint32_t& r1,
                                          uint32_t& r2, uint32_t& r3, uint32_t addr) {
    asm volatile("ldmatrix.sync.aligned.m8n8.x4.trans.shared.b16 {%0,%1,%2,%3}, [%4];"
                 : "=r"(r0), "=r"(r1), "=r"(r2), "=r"(r3) : "r"(addr));
}
__device__ __forceinline__ uint32_t smem_u32(const void* p) {
    uint32_t a;
    asm("{ .reg .u64 t; cvta.to.shared.u64 t, %1; cvt.u32.u64 %0, t; }" : "=r"(a) : "l"(p));
    return a;
}
__device__ __forceinline__ void cp16(uint32_t dst, const void* src) {
    asm volatile("cp.async.cg.shared.global [%0], [%1], 16;" :: "r"(dst), "l"(src) : "memory");
}
__device__ __forceinline__ void cp_commit() {
    asm volatile("cp.async.commit_group;" ::: "memory");
}
__device__ __forceinline__ void cp_wait1() {
    asm volatile("cp.async.wait_group 1;" ::: "memory");
}
__device__ __forceinline__ void cp_wait2() {
    asm volatile("cp.async.wait_group 2;" ::: "memory");
}

// =================================================================
// Pre-pass (single launch): RN-round fp32 -> fp16, 7 matrices.
// =================================================================
__global__ __launch_bounds__(256)
void prep_all(const float* __restrict__ q, const float* __restrict__ k,
              const float* __restrict__ v,
              const float* __restrict__ Wq, const float* __restrict__ Wk,
              const float* __restrict__ Wv, const float* __restrict__ Wo,
              __half* __restrict__ dstA, __half* __restrict__ dstW)
{
    const int z = blockIdx.z;
    const float* s;
    __half* d;
    int gpm;
    if (z < 3) {
        s = (z == 0) ? q : (z == 1) ? k : v;
        gpm = MROWS*DMODEL/16;
        d = dstA + (size_t)z * ((size_t)MROWS*DMODEL);
    } else {
        int w = z - 3;
        s = (w == 0) ? Wq : (w == 1) ? Wk : (w == 2) ? Wv : Wo;
        gpm = DMODEL*DMODEL/16;
        d = dstW + (size_t)w * ((size_t)DMODEL*DMODEL);
    }
    int i = blockIdx.x * blockDim.x + threadIdx.x;
    if (i >= gpm) return;
    const float4* sp = (const float4*)(s + (size_t)i * 16);
    float4 a = sp[0], b = sp[1], c = sp[2], e = sp[3];
    uint4* o = (uint4*)(d + (size_t)i * 16);
    o[0] = make_uint4(pack2(a.x, a.y), pack2(a.z, a.w),
                      pack2(b.x, b.y), pack2(b.z, b.w));
    o[1] = make_uint4(pack2(c.x, c.y), pack2(c.z, c.w),
                      pack2(e.x, e.y), pack2(e.z, e.w));
}

// =================================================================
// fp16 tensor GEMM v3 (unchanged from R15): 512 threads = 16 warps
//   (4m x 4n) of 32x32, CTA tile 128x128, BK=64, 3-stage cp.async.
// =================================================================
#define GSTR 72
#define GBUFH (128*GSTR)                // 9216 halves per operand buffer
#define GSTG  (2*GBUFH*2)               // stage bytes (A+B) = 36864
#define GT_SMEM_BYTES (3*GSTG)          // 110592 B

template<int MODE>
__global__ __launch_bounds__(512, 2)
void gemm_mma(const __half* __restrict__ Abase, const __half* __restrict__ Wbase,
              __half* __restrict__ H0, __half* __restrict__ H1, __half* __restrict__ H2,
              float* __restrict__ Cf)
{
    extern __shared__ __half smh[];
    const uint32_t smb = smem_u32(smh);

    const int z = blockIdx.z;
    const __half* A = Abase + (size_t)z * ((size_t)MROWS * DMODEL);
    const __half* W = Wbase + (size_t)z * ((size_t)DMODEL * DMODEL);

    const int tid  = threadIdx.x;
    const int wid  = tid >> 5;
    const int lane = tid & 31;
    const int g    = lane >> 2;
    const int tig  = lane & 3;
    const int wm   = wid & 3;
    const int wn   = wid >> 2;
    const int m0 = blockIdx.y * 128;
    const int n0 = blockIdx.x * 128;

    const int lr = tid >> 2;
    const int cb = (tid & 3) * 2;
    const __half* Asrc = A + (size_t)(m0 + lr) * DMODEL + cb * 8;
    const __half* Wsrc = W + (size_t)(n0 + lr) * DMODEL + cb * 8;
    const uint32_t aDst = smb + lr * (GSTR*2) + cb * 16;

    const uint32_t laneA_off = (uint32_t)(wm*32 + (lane & 15)) * (GSTR*2)
                             + (uint32_t)(lane >> 4) * 16;
    const uint32_t laneB_off = (uint32_t)(wn*32 + (lane & 7) + ((lane >> 4) & 1) * 8) * (GSTR*2)
                             + (uint32_t)((lane >> 3) & 1) * 16;

    float acc[2][4][4];
#pragma unroll
    for (int i = 0; i < 2; i++)
#pragma unroll
        for (int j = 0; j < 4; j++)
#pragma unroll
            for (int q = 0; q < 4; q++) acc[i][j][q] = 0.f;

#pragma unroll
    for (int j = 0; j < 2; j++) {
        cp16(aDst + j*16, Asrc + j*8);
        cp16(aDst + GBUFH*2 + j*16, Wsrc + j*8);
    }
    cp_commit();
#pragma unroll
    for (int j = 0; j < 2; j++) {
        cp16(aDst + GSTG + j*16, Asrc + 64 + j*8);
        cp16(aDst + GSTG + GBUFH*2 + j*16, Wsrc + 64 + j*8);
    }
    cp_commit();

    int st = 0;
    for (int c = 0; c < 16; c++) {
        cp_wait1();
        __syncthreads();
        {
            int st2 = st + 2; if (st2 >= 3) st2 -= 3;
            if (c + 2 < 16) {
                const __half* as = Asrc + (c+2)*64;
                const __half* ws = Wsrc + (c+2)*64;
                const uint32_t ad = aDst + st2 * GSTG;
#pragma unroll
                for (int j = 0; j < 2; j++) {
                    cp16(ad + j*16, as + j*8);
                    cp16(ad + GBUFH*2 + j*16, ws + j*8);
                }
            }
            cp_commit();
        }
        const uint32_t aBase = smb + st * GSTG + laneA_off;
        const uint32_t bBase = smb + st * GSTG + GBUFH*2 + laneB_off;
#pragma unroll
        for (int kg = 0; kg < 4; kg++) {
            uint32_t a[2][4];
#pragma unroll
            for (int mt = 0; mt < 2; mt++)
                ldsm_x4(a[mt][0], a[mt][1], a[mt][2], a[mt][3],
                        aBase + mt * (16*GSTR*2) + kg*32);
#pragma unroll
            for (int ntp = 0; ntp < 2; ntp++) {
                uint32_t b0, b1, b2, b3;
                ldsm_x4(b0, b1, b2, b3, bBase + ntp * (16*GSTR*2) + kg*32);
#pragma unroll
                for (int mt = 0; mt < 2; mt++) {
                    mma_f16(acc[mt][2*ntp  ], a[mt][0], a[mt][1], a[mt][2], a[mt][3], b0, b1);
                    mma_f16(acc[mt][2*ntp+1], a[mt][0], a[mt][1], a[mt][2], a[mt][3], b2, b3);
                }
            }
        }
        st++; if (st == 3) st = 0;
    }

    const float sc = (MODE == 0 && z == 0) ? QSCALE : 1.0f;
    __half* Hm = (z == 0) ? H0 : (z == 1) ? H1 : H2;
#pragma unroll
    for (int mt = 0; mt < 2; mt++) {
#pragma unroll
        for (int nt = 0; nt < 4; nt++) {
            int m = m0 + wm*32 + mt*16 + g;
            int n = n0 + wn*32 + nt*8 + 2*tig;
#pragma unroll
            for (int half_ = 0; half_ < 2; half_++) {
                int mm = m + half_*8;
                float vx = acc[mt][nt][half_*2];
                float vy = acc[mt][nt][half_*2+1];
                if (MODE == 0) {
                    int b = mm >> 11;
                    int l = mm & (SEQ - 1);
                    int h = n >> 6;
                    int d = n & (HDIM - 1);
                    size_t base = ((size_t)((b*NHEAD + h)*SEQ) + l) * HDIM;
                    *(__half2*)&Hm[base + d] = __floats2half2_rn(vx*sc, vy*sc);
                } else {
                    *(float2*)&Cf[(size_t)mm * DMODEL + n] = make_float2(vx, vy);
                }
            }
        }
    }
}

// =================================================================
// Flash attention v11: fp16, log2 softmax (f32 ex2), 256 thr =
// 8 warps x 16 q, 128 q/block, 64-key chunks, 3-stage cp.async,
// ldmatrix fragments. l via FADD+shfl (off the tensor pipe).
// =================================================================
#define FQS 72
#define FA_Q (128*FQS)                 // 9216 halves
#define FA_K (64*FQS)                  // 4608
#define FA_V (64*FQS)                  // 4608
#define FA_SMEM_BYTES ((FA_Q + 3*FA_K + 3*FA_V)*2)   // 73728 B

__global__ __launch_bounds__(256, 2)
void flash_mma(const int* __restrict__ mask,
               const __half* __restrict__ Qg,
               const __half* __restrict__ Kg,
               const __half* __restrict__ Vg,
               __half* __restrict__ Og)
{
    extern __shared__ __half smh[];
    const uint32_t smb = smem_u32(smh);
    __shared__ int msk[64];

    const int tid  = threadIdx.x;
    const int lane = tid & 31;
    const int wid  = tid >> 5;
    const int g    = lane >> 2;
    const int tig  = lane & 3;
    const int qb   = wid * 16;

    const int bh = blockIdx.y;
    const int b  = bh / NHEAD;
    const int h  = bh % NHEAD;
    const int q0 = blockIdx.x * 128;

    const size_t bhBase = (size_t)(b*NHEAD + h) * SEQ * HDIM;

    const int lr2 = tid >> 2;
    const int cb2 = (tid & 3) * 2;
    const __half* Ksrc = Kg + bhBase + (size_t)lr2 * HDIM + cb2 * 8;
    const __half* Vsrc = Vg + bhBase + (size_t)lr2 * HDIM + cb2 * 8;
    const uint32_t kDst0 = smb + FA_Q*2 + lr2 * (FQS*2) + cb2 * 16;
    const uint32_t vDst0 = smb + (FA_Q + 3*FA_K)*2 + lr2 * (FQS*2) + cb2 * 16;

    const uint32_t laneQ_off = (uint32_t)(qb + (lane & 15)) * (FQS*2)
                             + (uint32_t)(lane >> 4) * 16;
    const uint32_t laneK_off = (uint32_t)((lane & 7) + ((lane >> 4) & 1) * 8) * (FQS*2)
                             + (uint32_t)((lane >> 3) & 1) * 16;
    const uint32_t laneV_off = (uint32_t)(lane & 15) * (FQS*2)
                             + (uint32_t)(lane >> 4) * 16;

    // ---- prologue: G0 = Q, G1 = KV0, G2 = KV1 ----
    {
        const int qr = tid >> 1;
        const int qc = (tid & 1) * 4;
        const __half* qsrc = Qg + bhBase + (size_t)(q0 + qr) * HDIM + qc * 8;
        uint32_t qdst = smb + qr * (FQS*2) + qc * 16;
#pragma unroll
        for (int j = 0; j < 4; j++) cp16(qdst + j*16, qsrc + j*8);
        cp_commit();   // G0
#pragma unroll
        for (int j = 0; j < 2; j++) {
            cp16(kDst0 + j*16, Ksrc + j*8);
            cp16(vDst0 + j*16, Vsrc + j*8);
        }
        cp_commit();   // G1
        const __half* ks1 = Ksrc + 64*HDIM;
        const __half* vs1 = Vsrc + 64*HDIM;
#pragma unroll
        for (int j = 0; j < 2; j++) {
            cp16(kDst0 + FA_K*2 + j*16, ks1 + j*8);
            cp16(vDst0 + FA_V*2 + j*16, vs1 + j*8);
        }
        cp_commit();   // G2
    }

    // ---- whole-sequence mask precheck ----
    int sv = 1;
#pragma unroll
    for (int j = 0; j < 8; j++)
        sv &= (mask[b*SEQ + tid + j*256] != 0);
    const int allSeq = __syncthreads_and(sv);
    int mreg = 0;
    if (!allSeq && tid < 64) mreg = mask[b*SEQ + tid];

    // ---- Q fragments to registers (once) ----
    cp_wait2();
    __syncthreads();
    uint32_t qa[4][4];
#pragma unroll
    for (int kg = 0; kg < 4; kg++)
        ldsm_x4(qa[kg][0], qa[kg][1], qa[kg][2], qa[kg][3],
                smb + laneQ_off + kg*32);

    float o[8][4];
#pragma unroll
    for (int nt = 0; nt < 8; nt++)
#pragma unroll
        for (int q = 0; q < 4; q++) o[nt][q] = 0.f;
    float lrow0 = 0.f, lrow1 = 0.f;
    float mrow0 = -1e30f, mrow1 = -1e30f;

    int st = 0;
    for (int c = 0; c < 32; c++) {
        cp_wait1();
        int allv;
        if (!allSeq) {
            if (tid < 64) msk[tid] = mreg;
            int curv = (tid < 64) ? (mreg != 0) : 1;
            if (c + 1 < 32 && tid < 64) mreg = mask[b*SEQ + (c+1)*64 + tid];
            allv = __syncthreads_and(curv);
        } else {
            __syncthreads();
            allv = 1;
        }

        // issue chunk c+2 (always commit to keep wait accounting)
        {
            int st2 = st + 2; if (st2 >= 3) st2 -= 3;
            if (c + 2 < 32) {
                const __half* ks = Ksrc + (size_t)(c+2) * 64 * HDIM;
                const __half* vs = Vsrc + (size_t)(c+2) * 64 * HDIM;
                const uint32_t kd = kDst0 + st2 * (FA_K*2);
                const uint32_t vd = vDst0 + st2 * (FA_V*2);
#pragma unroll
                for (int j = 0; j < 2; j++) {
                    cp16(kd + j*16, ks + j*8);
                    cp16(vd + j*16, vs + j*8);
                }
            }
            cp_commit();
        }

        const uint32_t kBase = smb + FA_Q*2 + st * (FA_K*2) + laneK_off;

        // ---- S = Q K^T ----
        float s[8][4];
#pragma unroll
        for (int nt = 0; nt < 8; nt++)
#pragma unroll
            for (int q = 0; q < 4; q++) s[nt][q] = 0.f;

#pragma unroll
        for (int kg = 0; kg < 4; kg++) {
#pragma unroll
            for (int ntp = 0; ntp < 4; ntp++) {
                uint32_t b0, b1, b2, b3;
                ldsm_x4(b0, b1, b2, b3, kBase + ntp * (16*FQS*2) + kg*32);
                mma_f16(s[2*ntp  ], qa[kg][0], qa[kg][1], qa[kg][2], qa[kg][3], b0, b1);
                mma_f16(s[2*ntp+1], qa[kg][0], qa[kg][1], qa[kg][2], qa[kg][3], b2, b3);
            }
        }

        // ---- mask (skipped when chunk fully valid) ----
        if (!allv) {
#pragma unroll
            for (int nt = 0; nt < 8; nt++) {
                int j0 = nt*8 + 2*tig;
                bool k0 = (msk[j0]   != 0);
                bool k1 = (msk[j0+1] != 0);
                s[nt][0] = k0 ? s[nt][0] : NEG_INF_V;
                s[nt][1] = k1 ? s[nt][1] : NEG_INF_V;
                s[nt][2] = k0 ? s[nt][2] : NEG_INF_V;
                s[nt][3] = k1 ? s[nt][3] : NEG_INF_V;
            }
        }

        // ---- online softmax (log2 domain, f32 ex2) ----
        float rm0 = -1e30f, rm1 = -1e30f;
#pragma unroll
        for (int nt = 0; nt < 8; nt++) {
            rm0 = fmaxf(rm0, fmaxf(s[nt][0], s[nt][1]));
            rm1 = fmaxf(rm1, fmaxf(s[nt][2], s[nt][3]));
        }
        rm0 = fmaxf(rm0, __shfl_xor_sync(0xffffffffu, rm0, 1));
        rm0 = fmaxf(rm0, __shfl_xor_sync(0xffffffffu, rm0, 2));
        rm1 = fmaxf(rm1, __shfl_xor_sync(0xffffffffu, rm1, 1));
        rm1 = fmaxf(rm1, __shfl_xor_sync(0xffffffffu, rm1, 2));

        float mn0 = fmaxf(mrow0, rm0);
        float mn1 = fmaxf(mrow1, rm1);
        bool stable = __all_sync(0xffffffffu, (mn0 == mrow0) && (mn1 == mrow1));
        if (!stable) {
            float fac0 = ex2f(mrow0 - mn0);
            float fac1 = ex2f(mrow1 - mn1);
            lrow0 *= fac0;
            lrow1 *= fac1;
#pragma unroll
            for (int nt = 0; nt < 8; nt++) {
                o[nt][0] *= fac0; o[nt][1] *= fac0;
                o[nt][2] *= fac1; o[nt][3] *= fac1;
            }
            mrow0 = mn0;
            mrow1 = mn1;
        }

        // exp (f32), row-sum on fma pipe
        float rs0 = 0.f, rs1 = 0.f;
#pragma unroll
        for (int nt = 0; nt < 8; nt++) {
            s[nt][0] = ex2f(s[nt][0] - mrow0);
            s[nt][1] = ex2f(s[nt][1] - mrow0);
            s[nt][2] = ex2f(s[nt][2] - mrow1);
            s[nt][3] = ex2f(s[nt][3] - mrow1);
            rs0 += s[nt][0] + s[nt][1];
            rs1 += s[nt][2] + s[nt][3];
        }
        rs0 += __shfl_xor_sync(0xffffffffu, rs0, 1);
        rs0 += __shfl_xor_sync(0xffffffffu, rs0, 2);
        rs1 += __shfl_xor_sync(0xffffffffu, rs1, 1);
        rs1 += __shfl_xor_sync(0xffffffffu, rs1, 2);
        lrow0 += rs0;
        lrow1 += rs1;

        // ---- O += P V (pack P to fp16; ldmatrix.trans B) ----
        const uint32_t vBase = smb + (FA_Q + 3*FA_K)*2 + st * (FA_V*2) + laneV_off;
#pragma unroll
        for (int kg = 0; kg < 4; kg++) {
            uint32_t a0 = pack2(s[2*kg  ][0], s[2*kg  ][1]);
            uint32_t a1 = pack2(s[2*kg  ][2], s[2*kg  ][3]);
            uint32_t a2 = pack2(s[2*kg+1][0], s[2*kg+1][1]);
            uint32_t a3 = pack2(s[2*kg+1][2], s[2*kg+1][3]);
            const uint32_t rowa = vBase + kg * (16*FQS*2);
#pragma unroll
            for (int ntp = 0; ntp < 4; ntp++) {
                uint32_t r0, r1, r2, r3;
                ldsm_x4_t(r0, r1, r2, r3, rowa + ntp*32);
                mma_f16(o[2*ntp  ], a0, a1, a2, a3, r0, r1);
                mma_f16(o[2*ntp+1], a0, a1, a2, a3, r2, r3);
            }
        }

        st++; if (st == 3) st = 0;
    }

    // ---- epilogue: normalize, fp16 -> g_O [B,L,D] (natural) ----
    float inv0 = 1.f / lrow0;
    float inv1 = 1.f / lrow1;
    int qg0 = q0 + qb + g;
    int qg1 = qg0 + 8;
#pragma unroll
    for (int nt = 0; nt < 8; nt++) {
        int pos = h*HDIM + nt*8 + 2*tig;
        *(__half2*)&Og[(size_t)(b*SEQ + qg0)*DMODEL + pos] =
            __floats2half2_rn(o[nt][0]*inv0, o[nt][1]*inv0);
        *(__half2*)&Og[(size_t)(b*SEQ + qg1)*DMODEL + pos] =
            __floats2half2_rn(o[nt][2]*inv1, o[nt][3]*inv1);
    }
}

// =================================================================
// Host launcher
// =================================================================
extern "C" void kernel_launch(void* const* d_in, const int* in_sizes, int n_in,
                              void* d_out, int out_size)
{
    const float* q    = (const float*)d_in[0];
    const float* k    = (const float*)d_in[1];
    const float* v    = (const float*)d_in[2];
    const int*   am   = (const int*)  d_in[3];
    const float* Wq   = (const float*)d_in[4];
    const float* Wk   = (const float*)d_in[5];
    const float* Wv   = (const float*)d_in[6];
    const float* Wo   = (const float*)d_in[7];
    float* out = (float*)d_out;

    __half *gA, *gW, *gQ, *gK, *gV, *gO;
    cudaGetSymbolAddress((void**)&gA, g_A);
    cudaGetSymbolAddress((void**)&gW, g_W);
    cudaGetSymbolAddress((void**)&gQ, g_Q);
    cudaGetSymbolAddress((void**)&gK, g_K);
    cudaGetSymbolAddress((void**)&gV, g_V);
    cudaGetSymbolAddress((void**)&gO, g_O);

    cudaFuncSetAttribute(gemm_mma<0>, cudaFuncAttributeMaxDynamicSharedMemorySize, GT_SMEM_BYTES);
    cudaFuncSetAttribute(gemm_mma<1>, cudaFuncAttributeMaxDynamicSharedMemorySize, GT_SMEM_BYTES);
    cudaFuncSetAttribute(flash_mma,   cudaFuncAttributeMaxDynamicSharedMemorySize, FA_SMEM_BYTES);

    // pre-pass: fp16 round, all 7 matrices in one launch
    {
        int gpmA = MROWS*DMODEL/16;    // 262144 groups (largest)
        dim3 pg((gpmA + 255)/256, 1, 7);
        prep_all<<<pg, 256>>>(q, k, v, Wq, Wk, Wv, Wo, gA, gW);
    }

    // fused QKV projections (512-thread CTAs, 3-stage pipeline)
    dim3 gGrid(DMODEL/128, MROWS/128, 3);  // (8, 32, 3)
    gemm_mma<0><<<gGrid, 512, GT_SMEM_BYTES>>>(gA, gW, gQ, gK, gV, out);

    dim3 aGrid(SEQ/128, BATCH*NHEAD);      // (16, 32)
    flash_mma<<<aGrid, 256, FA_SMEM_BYTES>>>(am, gQ, gK, gV, gO);

    dim3 oGrid(DMODEL/128, MROWS/128, 1);  // (8, 32)
    gemm_mma<1><<<oGrid, 512, GT_SMEM_BYTES>>>(gO, gW + 3u*DMODEL*DMODEL,
                                               gQ, gK, gV, out);
}